// round 3
// baseline (speedup 1.0000x reference)
#include <cuda_runtime.h>

#define BB 16
#define TT 2048
#define CC 288
#define CC4 (CC/4)
#define HS 32
#define NROWS (BB*TT)
#define ROWS 128          // t rows per attn block
#define TSW  128          // s-tile staged in smem
#define SC   512          // s-chunk per block (split-s)
#define NC   (TT/SC)      // 4 chunks
// 32^-0.5 * log2(e)
#define SCLOG2E 0.25506551f

typedef unsigned long long u64;

// ---- scratch (device globals; cudaMalloc forbidden) ----
__device__ float  g_k[NROWS*HS];
__device__ float  g_q[NROWS*HS];
__device__ float  g_v[NROWS*HS];
__device__ float  g_wt[3*HS*CC];                 // W transposed: [proj][h][c]
__device__ float  g_pacc[(size_t)NC*NROWS*HS];   // split-s partial P·V
__device__ float  g_pden[NC*NROWS];              // split-s partial sum(exp)

// ---- packed f32x2 helpers ----
__device__ __forceinline__ u64 fma2(u64 a, u64 b, u64 c) {
    u64 d; asm("fma.rn.f32x2 %0,%1,%2,%3;" : "=l"(d) : "l"(a), "l"(b), "l"(c)); return d;
}
__device__ __forceinline__ u64 add2(u64 a, u64 b) {
    u64 d; asm("add.rn.f32x2 %0,%1,%2;" : "=l"(d) : "l"(a), "l"(b)); return d;
}
__device__ __forceinline__ u64 pack2(float lo, float hi) {
    u64 d; asm("mov.b64 %0,{%1,%2};" : "=l"(d) : "f"(lo), "f"(hi)); return d;
}
__device__ __forceinline__ float2 unpack2(u64 a) {
    float lo, hi; asm("mov.b64 {%0,%1},%2;" : "=f"(lo), "=f"(hi) : "l"(a));
    return make_float2(lo, hi);
}
__device__ __forceinline__ float ex2f(float x) {
    float r; asm("ex2.approx.ftz.f32 %0,%1;" : "=f"(r) : "f"(x)); return r;
}

// ---- (tile, chunk) work list: full-work pairs first. tile low byte, chunk<<8 ----
static __device__ const int g_pairs[40] = {
    3,4,5,6,7,8,9,10,11,12,13,14,15,             // chunk 0 full
    263,264,265,266,267,268,269,270,271,          // chunk 1 full
    523,524,525,526,527,                          // chunk 2 full
    783,                                          // chunk 3 full
    0,1,2, 260,261,262, 520,521,522, 780,781,782  // partials (shortest last)
};

// -------------------------------------------------------------------------
// Prepack: transpose W so each h-column is contiguous over c. This makes the
// proj kernel's weight loads deliver ready-packed f32x2 operands.
// -------------------------------------------------------------------------
__global__ void prepack_kernel(const float* __restrict__ Wk,
                               const float* __restrict__ Wq,
                               const float* __restrict__ Wv) {
    int i = blockIdx.x * 256 + threadIdx.x;
    if (i >= CC * HS) return;
    int c = i / HS, h = i % HS;
    g_wt[(0 * HS + h) * CC + c] = Wk[i];
    g_wt[(1 * HS + h) * CC + c] = Wq[i];
    g_wt[(2 * HS + h) * CC + c] = Wv[i];
}

// -------------------------------------------------------------------------
// Projection. Block (32,8): 32 rows of x in smem (as ulonglong2 so LDS.128
// yields packed pairs). Thread (h, r) computes dim h of rows r, r+8, r+16,
// r+24 for all three projections. Per 4-c step: 4 LDS.128 + 3 LDG.128 +
// 24 FFMA2, zero pack instructions.
// -------------------------------------------------------------------------
#define PR 32
__global__ void proj_kernel(const float* __restrict__ x) {
    __shared__ ulonglong2 xs[PR * CC4];            // 36 KB
    int row0 = blockIdx.x * PR;
    int tid = threadIdx.y * 32 + threadIdx.x;
    const ulonglong2* xr = (const ulonglong2*)(x + (size_t)row0 * CC);
    for (int i = tid; i < PR * CC4; i += 256) xs[i] = xr[i];
    __syncthreads();

    int h = threadIdx.x, r = threadIdx.y;
    const ulonglong2* wk = (const ulonglong2*)(g_wt + (0 * HS + h) * CC);
    const ulonglong2* wq = (const ulonglong2*)(g_wt + (1 * HS + h) * CC);
    const ulonglong2* wv = (const ulonglong2*)(g_wt + (2 * HS + h) * CC);
    const ulonglong2* x0 = xs + (r)      * CC4;
    const ulonglong2* x1 = xs + (r + 8)  * CC4;
    const ulonglong2* x2 = xs + (r + 16) * CC4;
    const ulonglong2* x3 = xs + (r + 24) * CC4;

    u64 ak[4] = {0,0,0,0}, aq[4] = {0,0,0,0}, av[4] = {0,0,0,0};
#pragma unroll 4
    for (int c4 = 0; c4 < CC4; c4++) {
        ulonglong2 wkv = wk[c4], wqv = wq[c4], wvv = wv[c4];
        ulonglong2 xv;
        xv = x0[c4];
        ak[0]=fma2(xv.x,wkv.x,ak[0]); ak[0]=fma2(xv.y,wkv.y,ak[0]);
        aq[0]=fma2(xv.x,wqv.x,aq[0]); aq[0]=fma2(xv.y,wqv.y,aq[0]);
        av[0]=fma2(xv.x,wvv.x,av[0]); av[0]=fma2(xv.y,wvv.y,av[0]);
        xv = x1[c4];
        ak[1]=fma2(xv.x,wkv.x,ak[1]); ak[1]=fma2(xv.y,wkv.y,ak[1]);
        aq[1]=fma2(xv.x,wqv.x,aq[1]); aq[1]=fma2(xv.y,wqv.y,aq[1]);
        av[1]=fma2(xv.x,wvv.x,av[1]); av[1]=fma2(xv.y,wvv.y,av[1]);
        xv = x2[c4];
        ak[2]=fma2(xv.x,wkv.x,ak[2]); ak[2]=fma2(xv.y,wkv.y,ak[2]);
        aq[2]=fma2(xv.x,wqv.x,aq[2]); aq[2]=fma2(xv.y,wqv.y,aq[2]);
        av[2]=fma2(xv.x,wvv.x,av[2]); av[2]=fma2(xv.y,wvv.y,av[2]);
        xv = x3[c4];
        ak[3]=fma2(xv.x,wkv.x,ak[3]); ak[3]=fma2(xv.y,wkv.y,ak[3]);
        aq[3]=fma2(xv.x,wqv.x,aq[3]); aq[3]=fma2(xv.y,wqv.y,aq[3]);
        av[3]=fma2(xv.x,wvv.x,av[3]); av[3]=fma2(xv.y,wvv.y,av[3]);
    }
#pragma unroll
    for (int rr = 0; rr < 4; rr++) {
        int base = (row0 + r + rr * 8) * HS + h;
        float2 k2 = unpack2(ak[rr]); g_k[base] = k2.x + k2.y;
        float2 q2 = unpack2(aq[rr]); g_q[base] = q2.x + q2.y;
        float2 v2 = unpack2(av[rr]); g_v[base] = v2.x + v2.y;
    }
}

// -------------------------------------------------------------------------
// Attention partials over an s-chunk. weights = k @ q^T (reference quirk),
// causal s <= t, no max-subtraction (scores O(5), fp32-safe) so split-s
// partials combine by plain addition. Packed f32x2 throughout; unroll-2 on
// the s-loop for cross-iteration ILP.
// -------------------------------------------------------------------------
__global__ void __launch_bounds__(ROWS) attn_kernel() {
    int pr = g_pairs[blockIdx.x];
    int tile = pr & 0xff;
    int c = pr >> 8;
    int b = blockIdx.y;
    int t0 = tile * ROWS;
    int t = t0 + threadIdx.x;
    size_t rowbase = (size_t)b * TT;

    const ulonglong2* k2 = (const ulonglong2*)(g_k + (rowbase + t) * HS);
    ulonglong2 kt2[8];
#pragma unroll
    for (int i = 0; i < 8; i++) kt2[i] = k2[i];

    ulonglong2 acc[8];
#pragma unroll
    for (int i = 0; i < 8; i++) { acc[i].x = 0ull; acc[i].y = 0ull; }
    float denom = 0.f;

    __shared__ ulonglong2 qs[TSW * 8];
    __shared__ ulonglong2 vs[TSW * 8];

    int s_begin = c * SC;
    int s_end = SC * (c + 1);
    if (s_end > t0 + ROWS) s_end = t0 + ROWS;

    for (int s0 = s_begin; s0 < s_end; s0 += TSW) {
        __syncthreads();
        const ulonglong2* q2 = (const ulonglong2*)(g_q + (rowbase + s0) * HS);
        const ulonglong2* v2 = (const ulonglong2*)(g_v + (rowbase + s0) * HS);
        for (int i = threadIdx.x; i < TSW * 8; i += ROWS) {
            qs[i] = q2[i];
            vs[i] = v2[i];
        }
        __syncthreads();

        int jmax = t - s0 + 1;                  // causal
        if (jmax > TSW) jmax = TSW;
#pragma unroll 2
        for (int j = 0; j < jmax; j++) {
            const ulonglong2* qj = qs + j * 8;
            u64 p0 = 0, p1 = 0, p2 = 0, p3 = 0;
#pragma unroll
            for (int i = 0; i < 8; i += 2) {
                ulonglong2 qa = qj[i], qb = qj[i + 1];
                p0 = fma2(kt2[i].x,     qa.x, p0);
                p1 = fma2(kt2[i].y,     qa.y, p1);
                p2 = fma2(kt2[i + 1].x, qb.x, p2);
                p3 = fma2(kt2[i + 1].y, qb.y, p3);
            }
            float2 pf = unpack2(add2(add2(p0, p1), add2(p2, p3)));
            float p = ex2f((pf.x + pf.y) * SCLOG2E);
            denom += p;
            u64 pp = pack2(p, p);
            const ulonglong2* vj = vs + j * 8;
#pragma unroll
            for (int i = 0; i < 8; i++) {
                ulonglong2 vv = vj[i];
                acc[i].x = fma2(pp, vv.x, acc[i].x);
                acc[i].y = fma2(pp, vv.y, acc[i].y);
            }
        }
    }

    size_t row = rowbase + t;
    ulonglong2* pa = (ulonglong2*)(g_pacc + ((size_t)c * NROWS + row) * HS);
#pragma unroll
    for (int i = 0; i < 8; i++) pa[i] = acc[i];
    g_pden[c * NROWS + row] = denom;
}

// -------------------------------------------------------------------------
// Combine split-s partials and normalize. One float4 per thread (8 threads
// per row) for 8x the memory parallelism of the row-per-thread version.
// -------------------------------------------------------------------------
__global__ void combine_kernel(float* __restrict__ out) {
    int gid = blockIdx.x * 256 + threadIdx.x;     // NROWS*8 threads
    int row = gid >> 3;
    int q = gid & 7;
    int t = row & (TT - 1);
    int cmax = t / SC;
    float4 a = make_float4(0.f, 0.f, 0.f, 0.f);
    float den = 0.f;
    const float4* pacc4 = (const float4*)g_pacc;
    for (int c = 0; c <= cmax; c++) {
        den += g_pden[c * NROWS + row];
        float4 v = pacc4[((size_t)c * NROWS + row) * 8 + q];
        a.x += v.x; a.y += v.y; a.z += v.z; a.w += v.w;
    }
    float rinv = 1.f / den;
    ((float4*)out)[(size_t)row * 8 + q] =
        make_float4(a.x * rinv, a.y * rinv, a.z * rinv, a.w * rinv);
}

extern "C" void kernel_launch(void* const* d_in, const int* in_sizes, int n_in,
                              void* d_out, int out_size) {
    const float* x  = (const float*)d_in[0];
    const float* Wk = (const float*)d_in[1];
    const float* Wq = (const float*)d_in[2];
    const float* Wv = (const float*)d_in[3];
    float* out = (float*)d_out;

    prepack_kernel<<<(CC * HS + 255) / 256, 256>>>(Wk, Wq, Wv);

    dim3 pb(32, 8);
    proj_kernel<<<NROWS / PR, pb>>>(x);

    dim3 ag(40, BB);
    attn_kernel<<<ag, ROWS>>>();

    combine_kernel<<<NROWS * 8 / 256, 256>>>(out);
}

// round 4
// speedup vs baseline: 1.7733x; 1.7733x over previous
#include <cuda_runtime.h>

#define BB 16
#define TT 2048
#define CC 288
#define CC4 (CC/4)
#define HS 32
#define NROWS (BB*TT)
#define ROWS 128          // t rows per attn block
#define TSW  128          // s-tile staged in smem
#define SC   512          // s-chunk per block (split-s)
#define NC   (TT/SC)      // 4 chunks
#define QKSCALE 0.17677669529663687f   // 32^-0.5, folded into Wk

typedef unsigned long long u64;

// ---- scratch (device globals; cudaMalloc forbidden) ----
__device__ float      g_k[NROWS*HS];             // pre-scaled by QKSCALE
__device__ float      g_q[NROWS*HS];
__device__ float      g_v[NROWS*HS];
__device__ ulonglong2 g_wq[3*CC4*HS];            // [proj][c4][h]: 4 packed w's
__device__ float      g_pacc[(size_t)NC*NROWS*HS];
__device__ float      g_pden[NC*NROWS];

// ---- packed f32x2 helpers ----
__device__ __forceinline__ u64 fma2(u64 a, u64 b, u64 c) {
    u64 d; asm("fma.rn.f32x2 %0,%1,%2,%3;" : "=l"(d) : "l"(a), "l"(b), "l"(c)); return d;
}
__device__ __forceinline__ u64 add2(u64 a, u64 b) {
    u64 d; asm("add.rn.f32x2 %0,%1,%2;" : "=l"(d) : "l"(a), "l"(b)); return d;
}
__device__ __forceinline__ u64 pack2(float lo, float hi) {
    u64 d; asm("mov.b64 %0,{%1,%2};" : "=l"(d) : "f"(lo), "f"(hi)); return d;
}
__device__ __forceinline__ float2 unpack2(u64 a) {
    float lo, hi; asm("mov.b64 {%0,%1},%2;" : "=f"(lo), "=f"(hi) : "l"(a));
    return make_float2(lo, hi);
}

// ---- (tile, chunk) work list: full-work pairs first. tile low byte, chunk<<8 ----
static __device__ const int g_pairs[40] = {
    3,4,5,6,7,8,9,10,11,12,13,14,15,              // chunk 0 full
    263,264,265,266,267,268,269,270,271,          // chunk 1 full
    523,524,525,526,527,                          // chunk 2 full
    783,                                          // chunk 3 full
    0,1,2, 260,261,262, 520,521,522, 780,781,782  // partials (shortest last)
};

// -------------------------------------------------------------------------
// Prepack: W quads, c-major per h lane, so proj's W loads are coalesced
// LDG.128 delivering ready-packed f32x2 operand pairs. Wk pre-scaled.
// -------------------------------------------------------------------------
__global__ void prepack_kernel(const float* __restrict__ Wk,
                               const float* __restrict__ Wq,
                               const float* __restrict__ Wv) {
    int i = blockIdx.x * 256 + threadIdx.x;
    if (i >= 3 * CC4 * HS) return;
    int h = i & (HS - 1);
    int c4 = (i >> 5) % CC4;
    int p = i / (CC4 * HS);
    const float* W = (p == 0) ? Wk : (p == 1) ? Wq : Wv;
    float s = (p == 0) ? QKSCALE : 1.0f;
    float w0 = W[(4 * c4 + 0) * HS + h] * s;
    float w1 = W[(4 * c4 + 1) * HS + h] * s;
    float w2 = W[(4 * c4 + 2) * HS + h] * s;
    float w3 = W[(4 * c4 + 3) * HS + h] * s;
    ulonglong2 r; r.x = pack2(w0, w1); r.y = pack2(w2, w3);
    g_wq[i] = r;
}

// -------------------------------------------------------------------------
// Projection. Block (32,8): 32 rows of x in smem as u64 c-pairs. Thread
// (h, r) computes dim h of rows r, r+8, r+16, r+24 for all 3 projections.
// Per c4: 3 coalesced LDG.128 (W quads) + 4 broadcast LDS.128 (x) + 24 FMA2.
// -------------------------------------------------------------------------
#define PR 32
__global__ void proj_kernel(const float* __restrict__ x) {
    __shared__ ulonglong2 xs[PR * CC4];            // 36 KB
    int row0 = blockIdx.x * PR;
    int tid = threadIdx.y * 32 + threadIdx.x;
    const ulonglong2* xr = (const ulonglong2*)(x + (size_t)row0 * CC);
    for (int i = tid; i < PR * CC4; i += 256) xs[i] = xr[i];
    __syncthreads();

    int h = threadIdx.x, r = threadIdx.y;
    const ulonglong2* x0 = xs + (r)      * CC4;
    const ulonglong2* x1 = xs + (r + 8)  * CC4;
    const ulonglong2* x2 = xs + (r + 16) * CC4;
    const ulonglong2* x3 = xs + (r + 24) * CC4;

    u64 ak[4] = {0,0,0,0}, aq[4] = {0,0,0,0}, av[4] = {0,0,0,0};
#pragma unroll 4
    for (int c4 = 0; c4 < CC4; c4++) {
        ulonglong2 wk = g_wq[(0 * CC4 + c4) * HS + h];
        ulonglong2 wq = g_wq[(1 * CC4 + c4) * HS + h];
        ulonglong2 wv = g_wq[(2 * CC4 + c4) * HS + h];
        ulonglong2 xv;
        xv = x0[c4];
        ak[0]=fma2(xv.x,wk.x,ak[0]); ak[0]=fma2(xv.y,wk.y,ak[0]);
        aq[0]=fma2(xv.x,wq.x,aq[0]); aq[0]=fma2(xv.y,wq.y,aq[0]);
        av[0]=fma2(xv.x,wv.x,av[0]); av[0]=fma2(xv.y,wv.y,av[0]);
        xv = x1[c4];
        ak[1]=fma2(xv.x,wk.x,ak[1]); ak[1]=fma2(xv.y,wk.y,ak[1]);
        aq[1]=fma2(xv.x,wq.x,aq[1]); aq[1]=fma2(xv.y,wq.y,aq[1]);
        av[1]=fma2(xv.x,wv.x,av[1]); av[1]=fma2(xv.y,wv.y,av[1]);
        xv = x2[c4];
        ak[2]=fma2(xv.x,wk.x,ak[2]); ak[2]=fma2(xv.y,wk.y,ak[2]);
        aq[2]=fma2(xv.x,wq.x,aq[2]); aq[2]=fma2(xv.y,wq.y,aq[2]);
        av[2]=fma2(xv.x,wv.x,av[2]); av[2]=fma2(xv.y,wv.y,av[2]);
        xv = x3[c4];
        ak[3]=fma2(xv.x,wk.x,ak[3]); ak[3]=fma2(xv.y,wk.y,ak[3]);
        aq[3]=fma2(xv.x,wq.x,aq[3]); aq[3]=fma2(xv.y,wq.y,aq[3]);
        av[3]=fma2(xv.x,wv.x,av[3]); av[3]=fma2(xv.y,wv.y,av[3]);
    }
#pragma unroll
    for (int rr = 0; rr < 4; rr++) {
        int base = (row0 + r + rr * 8) * HS + h;
        float2 f;
        f = unpack2(ak[rr]); g_k[base] = f.x + f.y;
        f = unpack2(aq[rr]); g_q[base] = f.x + f.y;
        f = unpack2(av[rr]); g_v[base] = f.x + f.y;
    }
}

// -------------------------------------------------------------------------
// Attention partials over an s-chunk. weights = k @ q^T (reference quirk),
// causal s <= t, no max-subtraction (scores O(5), fp32-safe) so split-s
// partials combine by plain addition. k pre-scaled so the dot IS the score.
// Manual 2-wide j interleave for two independent dot->exp chains in flight.
// -------------------------------------------------------------------------
__global__ void __launch_bounds__(ROWS, 4) attn_kernel() {
    int pr = g_pairs[blockIdx.x];
    int tile = pr & 0xff;
    int c = pr >> 8;
    int b = blockIdx.y;
    int t0 = tile * ROWS;
    int t = t0 + threadIdx.x;
    size_t rowbase = (size_t)b * TT;

    const ulonglong2* k2 = (const ulonglong2*)(g_k + (rowbase + t) * HS);
    ulonglong2 kt2[8];
#pragma unroll
    for (int i = 0; i < 8; i++) kt2[i] = k2[i];

    ulonglong2 acc[8];
#pragma unroll
    for (int i = 0; i < 8; i++) { acc[i].x = 0ull; acc[i].y = 0ull; }
    float denom = 0.f;

    __shared__ ulonglong2 qs[TSW * 8];
    __shared__ ulonglong2 vs[TSW * 8];

    int s_begin = c * SC;
    int s_end = SC * (c + 1);
    if (s_end > t0 + ROWS) s_end = t0 + ROWS;

    for (int s0 = s_begin; s0 < s_end; s0 += TSW) {
        __syncthreads();
        const ulonglong2* q2 = (const ulonglong2*)(g_q + (rowbase + s0) * HS);
        const ulonglong2* v2 = (const ulonglong2*)(g_v + (rowbase + s0) * HS);
        for (int i = threadIdx.x; i < TSW * 8; i += ROWS) {
            qs[i] = q2[i];
            vs[i] = v2[i];
        }
        __syncthreads();

        int jmax = t - s0 + 1;                  // causal
        if (jmax > TSW) jmax = TSW;
        int j = 0;
        for (; j + 2 <= jmax; j += 2) {
            const ulonglong2* qa = qs + j * 8;
            const ulonglong2* qb = qa + 8;
            u64 a0 = 0, a1 = 0, a2 = 0, a3 = 0;
            u64 b0 = 0, b1 = 0, b2 = 0, b3 = 0;
#pragma unroll
            for (int i = 0; i < 8; i += 2) {
                ulonglong2 qa0 = qa[i], qa1 = qa[i + 1];
                ulonglong2 qb0 = qb[i], qb1 = qb[i + 1];
                a0 = fma2(kt2[i].x,     qa0.x, a0);
                a1 = fma2(kt2[i].y,     qa0.y, a1);
                a2 = fma2(kt2[i + 1].x, qa1.x, a2);
                a3 = fma2(kt2[i + 1].y, qa1.y, a3);
                b0 = fma2(kt2[i].x,     qb0.x, b0);
                b1 = fma2(kt2[i].y,     qb0.y, b1);
                b2 = fma2(kt2[i + 1].x, qb1.x, b2);
                b3 = fma2(kt2[i + 1].y, qb1.y, b3);
            }
            float2 fa = unpack2(add2(add2(a0, a1), add2(a2, a3)));
            float2 fb = unpack2(add2(add2(b0, b1), add2(b2, b3)));
            float pA = __expf(fa.x + fa.y);
            float pB = __expf(fb.x + fb.y);
            denom += pA + pB;
            u64 ppA = pack2(pA, pA), ppB = pack2(pB, pB);
            const ulonglong2* va = vs + j * 8;
            const ulonglong2* vb = va + 8;
#pragma unroll
            for (int i = 0; i < 8; i++) {
                ulonglong2 v0 = va[i], v1 = vb[i];
                acc[i].x = fma2(ppB, v1.x, fma2(ppA, v0.x, acc[i].x));
                acc[i].y = fma2(ppB, v1.y, fma2(ppA, v0.y, acc[i].y));
            }
        }
        if (j < jmax) {                         // odd tail
            const ulonglong2* qa = qs + j * 8;
            u64 a0 = 0, a1 = 0, a2 = 0, a3 = 0;
#pragma unroll
            for (int i = 0; i < 8; i += 2) {
                ulonglong2 qa0 = qa[i], qa1 = qa[i + 1];
                a0 = fma2(kt2[i].x,     qa0.x, a0);
                a1 = fma2(kt2[i].y,     qa0.y, a1);
                a2 = fma2(kt2[i + 1].x, qa1.x, a2);
                a3 = fma2(kt2[i + 1].y, qa1.y, a3);
            }
            float2 fa = unpack2(add2(add2(a0, a1), add2(a2, a3)));
            float pA = __expf(fa.x + fa.y);
            denom += pA;
            u64 ppA = pack2(pA, pA);
            const ulonglong2* va = vs + j * 8;
#pragma unroll
            for (int i = 0; i < 8; i++) {
                ulonglong2 v0 = va[i];
                acc[i].x = fma2(ppA, v0.x, acc[i].x);
                acc[i].y = fma2(ppA, v0.y, acc[i].y);
            }
        }
    }

    size_t row = rowbase + t;
    ulonglong2* pa = (ulonglong2*)(g_pacc + ((size_t)c * NROWS + row) * HS);
#pragma unroll
    for (int i = 0; i < 8; i++) pa[i] = acc[i];
    g_pden[c * NROWS + row] = denom;
}

// -------------------------------------------------------------------------
// Combine split-s partials and normalize. One float4 per thread.
// -------------------------------------------------------------------------
__global__ void combine_kernel(float* __restrict__ out) {
    int gid = blockIdx.x * 256 + threadIdx.x;     // NROWS*8 threads
    int row = gid >> 3;
    int q = gid & 7;
    int t = row & (TT - 1);
    int cmax = t / SC;
    float4 a = make_float4(0.f, 0.f, 0.f, 0.f);
    float den = 0.f;
    const float4* pacc4 = (const float4*)g_pacc;
    for (int c = 0; c <= cmax; c++) {
        den += g_pden[c * NROWS + row];
        float4 v = pacc4[((size_t)c * NROWS + row) * 8 + q];
        a.x += v.x; a.y += v.y; a.z += v.z; a.w += v.w;
    }
    float rinv = 1.f / den;
    ((float4*)out)[(size_t)row * 8 + q] =
        make_float4(a.x * rinv, a.y * rinv, a.z * rinv, a.w * rinv);
}

extern "C" void kernel_launch(void* const* d_in, const int* in_sizes, int n_in,
                              void* d_out, int out_size) {
    const float* x  = (const float*)d_in[0];
    const float* Wk = (const float*)d_in[1];
    const float* Wq = (const float*)d_in[2];
    const float* Wv = (const float*)d_in[3];
    float* out = (float*)d_out;

    prepack_kernel<<<(3 * CC4 * HS + 255) / 256, 256>>>(Wk, Wq, Wv);

    dim3 pb(32, 8);
    proj_kernel<<<NROWS / PR, pb>>>(x);

    dim3 ag(40, BB);
    attn_kernel<<<ag, ROWS>>>();

    combine_kernel<<<NROWS * 8 / 256, 256>>>(out);
}